// round 16
// baseline (speedup 1.0000x reference)
#include <cuda_runtime.h>
#include <cuda_bf16.h>
#include <cuda_fp16.h>
#include <math.h>
#include <cstdint>

#define Bsz 2
#define Lsz 2048
#define Esz 1024
#define Hsz 16
#define Dsz 64
#define NROW 4096               // Bsz*Lsz
#define BLE  (Bsz*Lsz*Esz)      // 4,194,304
#define KE3  7168               // B width: 7 blocks
#define KA3  4096               // A width: 4 dedup blocks [Xr16|Xi16|Sh|Sl]
#define BHD  ((size_t)Bsz*Hsz*Lsz*Dsz)

// A (dedup): [Xr16 | Xi16 | Sh | Sl]  (fp16, fp16, bf16, bf16), S = Xr+Xi
// B: [W'rh W'rl | W'ih W'il | Wsh Wsl Wsh] (fp16 W'=W*256; bf16 Ws=Wr+Wi)
// acc0 = Xr·W'r (fp16), acc1 = Xi·W'i (fp16), acc2 = S·Ws (bf16)
// B-block -> A-block pairing: {0,0,1,1,2,2,3}
// Yr = (acc0-acc1)/256 + br ; Yi = acc2 - (acc0+acc1)/256 + bi
__device__ __nv_bfloat16 g_acat[3ull * NROW * KA3];           // 100 MB
__device__ __nv_bfloat16 g_bcat[4ull * Esz * KE3];            // 58.7 MB
// attention arrays: q(rh,rl,ih,il) k(4) bf16 ; v(rh,ih) fp16
__device__ __nv_bfloat16 g_attn[10ull * BHD];                 // 80 MB

// ---------------------------------------------------------------------------
// helpers
// ---------------------------------------------------------------------------
__device__ __forceinline__ uint32_t smem_u32(const void* p) {
    uint32_t a;
    asm("{ .reg .u64 t; cvta.to.shared.u64 t, %1; cvt.u32.u64 %0, t; }" : "=r"(a) : "l"(p));
    return a;
}
__device__ __forceinline__ void cpa16(uint32_t dst, const void* src) {
    asm volatile("cp.async.cg.shared.global [%0], [%1], 16;" :: "r"(dst), "l"(src));
}
#define CPA_COMMIT() asm volatile("cp.async.commit_group;" ::: "memory")
#define CPA_WAIT(n)  asm volatile("cp.async.wait_group %0;" :: "n"(n) : "memory")

__device__ __forceinline__ void ldsm_x4(uint32_t* r, uint32_t addr) {
    asm volatile("ldmatrix.sync.aligned.m8n8.x4.shared.b16 {%0,%1,%2,%3}, [%4];"
        : "=r"(r[0]), "=r"(r[1]), "=r"(r[2]), "=r"(r[3]) : "r"(addr));
}
__device__ __forceinline__ void ldsm_x4_t(uint32_t* r, uint32_t addr) {
    asm volatile("ldmatrix.sync.aligned.m8n8.x4.trans.shared.b16 {%0,%1,%2,%3}, [%4];"
        : "=r"(r[0]), "=r"(r[1]), "=r"(r[2]), "=r"(r[3]) : "r"(addr));
}
__device__ __forceinline__ void mma16816(float* c, const uint32_t* a, const uint32_t* b) {
    asm volatile("mma.sync.aligned.m16n8k16.row.col.f32.bf16.bf16.f32 "
        "{%0,%1,%2,%3}, {%4,%5,%6,%7}, {%8,%9}, {%0,%1,%2,%3};"
        : "+f"(c[0]), "+f"(c[1]), "+f"(c[2]), "+f"(c[3])
        : "r"(a[0]), "r"(a[1]), "r"(a[2]), "r"(a[3]), "r"(b[0]), "r"(b[1]));
}
__device__ __forceinline__ void mma16816h(float* c, const uint32_t* a, const uint32_t* b) {
    asm volatile("mma.sync.aligned.m16n8k16.row.col.f32.f16.f16.f32 "
        "{%0,%1,%2,%3}, {%4,%5,%6,%7}, {%8,%9}, {%0,%1,%2,%3};"
        : "+f"(c[0]), "+f"(c[1]), "+f"(c[2]), "+f"(c[3])
        : "r"(a[0]), "r"(a[1]), "r"(a[2]), "r"(a[3]), "r"(b[0]), "r"(b[1]));
}
__device__ __forceinline__ float fexp2(float x) {
    float y;
    asm("ex2.approx.ftz.f32 %0, %1;" : "=f"(y) : "f"(x));
    return y;
}
__device__ __forceinline__ void split1(float x, __nv_bfloat16& h, __nv_bfloat16& l) {
    h = __float2bfloat16(x);
    l = __float2bfloat16(x - __bfloat162float(h));
}
__device__ __forceinline__ void h2split(float v, __half& h, __half& l) {
    h = __float2half(v);
    l = __float2half(v - __half2float(h));
}
__device__ __forceinline__ uint32_t packbf2(__nv_bfloat16 a, __nv_bfloat16 b) {
    __nv_bfloat162 t; t.x = a; t.y = b;
    return *(uint32_t*)&t;
}
__device__ __forceinline__ uint32_t packh2(float a, float b) {
    __half2 t = __floats2half2_rn(a, b);
    return *(uint32_t*)&t;
}
__device__ __forceinline__ uint32_t packhh(__half a, __half b) {
    __half2 t; t.x = a; t.y = b;
    return *(uint32_t*)&t;
}

// ---------------------------------------------------------------------------
// fused split kernels (z-batched)
// ---------------------------------------------------------------------------
struct SplitABatch { const float* Xr[3]; const float* Xi[3]; __nv_bfloat16* A[3]; };
struct SplitWBatch { const float* Wr[4]; const float* Wi[4]; __nv_bfloat16* B[4]; };

__global__ __launch_bounds__(256) void splitA_kernel(SplitABatch p)
{
    const int z = blockIdx.z;
    const float* __restrict__ Xr = p.Xr[z];
    const float* __restrict__ Xi = p.Xi[z];
    __nv_bfloat16* __restrict__ A = p.A[z];
    const int total = NROW * Esz / 4;
    int idx = blockIdx.x * 256 + threadIdx.x;
    const int stride = gridDim.x * 256;
    for (; idx < total; idx += stride) {
        const int m = idx >> 8;
        const int kq = (idx & 255) << 2;
        float4 xr = ((const float4*)Xr)[idx];
        float4 xi = ((const float4*)Xi)[idx];
        uint2 r16 = make_uint2(packh2(xr.x, xr.y), packh2(xr.z, xr.w));
        uint2 i16 = make_uint2(packh2(xi.x, xi.y), packh2(xi.z, xi.w));
        __nv_bfloat16 sh[4], sl[4];
        split1(xr.x + xi.x, sh[0], sl[0]); split1(xr.y + xi.y, sh[1], sl[1]);
        split1(xr.z + xi.z, sh[2], sl[2]); split1(xr.w + xi.w, sh[3], sl[3]);
        __nv_bfloat16* base = A + (size_t)m * KA3 + kq;
        *(uint2*)(base + 0)    = r16;
        *(uint2*)(base + 1024) = i16;
        *(uint2*)(base + 2048) = make_uint2(packbf2(sh[0], sh[1]), packbf2(sh[2], sh[3]));
        *(uint2*)(base + 3072) = make_uint2(packbf2(sl[0], sl[1]), packbf2(sl[2], sl[3]));
    }
}

__global__ __launch_bounds__(256) void splitW_kernel(SplitWBatch p)
{
    const int z = blockIdx.z;
    const float* __restrict__ Wr = p.Wr[z];
    const float* __restrict__ Wi = p.Wi[z];
    __nv_bfloat16* __restrict__ B = p.B[z];
    const int total = Esz * Esz / 4;
    int idx = blockIdx.x * 256 + threadIdx.x;
    const int stride = gridDim.x * 256;
    for (; idx < total; idx += stride) {
        const int n = idx >> 8;
        const int kq = (idx & 255) << 2;
        float4 wr = ((const float4*)Wr)[idx];
        float4 wi = ((const float4*)Wi)[idx];
        __half rh[4], rl[4], ih[4], il[4];
        h2split(wr.x * 256.f, rh[0], rl[0]); h2split(wr.y * 256.f, rh[1], rl[1]);
        h2split(wr.z * 256.f, rh[2], rl[2]); h2split(wr.w * 256.f, rh[3], rl[3]);
        h2split(wi.x * 256.f, ih[0], il[0]); h2split(wi.y * 256.f, ih[1], il[1]);
        h2split(wi.z * 256.f, ih[2], il[2]); h2split(wi.w * 256.f, ih[3], il[3]);
        __nv_bfloat16 sh[4], sl[4];
        split1(wr.x + wi.x, sh[0], sl[0]); split1(wr.y + wi.y, sh[1], sl[1]);
        split1(wr.z + wi.z, sh[2], sl[2]); split1(wr.w + wi.w, sh[3], sl[3]);
        __nv_bfloat16* b = B + (size_t)n * KE3 + kq;
        *(uint2*)(b + 0)    = make_uint2(packhh(rh[0], rh[1]), packhh(rh[2], rh[3]));
        *(uint2*)(b + 1024) = make_uint2(packhh(rl[0], rl[1]), packhh(rl[2], rl[3]));
        *(uint2*)(b + 2048) = make_uint2(packhh(ih[0], ih[1]), packhh(ih[2], ih[3]));
        *(uint2*)(b + 3072) = make_uint2(packhh(il[0], il[1]), packhh(il[2], il[3]));
        uint2 shv = make_uint2(packbf2(sh[0], sh[1]), packbf2(sh[2], sh[3]));
        uint2 slv = make_uint2(packbf2(sl[0], sl[1]), packbf2(sl[2], sl[3]));
        *(uint2*)(b + 4096) = shv;
        *(uint2*)(b + 5120) = slv;
        *(uint2*)(b + 6144) = shv;
    }
}

// ---------------------------------------------------------------------------
// Mixed Karatsuba GEMM. CTA 128x64, 256 threads (8 warps, 4m x 2n, warp 32x32).
// KCH=128 (8 k-steps/chunk), NCHK=56, 3-stage, single sync per chunk.
// chunk groups: acc0 fp16 (0-15), acc1 fp16 (16-31), acc2 bf16 (32-55).
// A dedup: per B-block map {0,0,1,1,2,2,3}.
// ---------------------------------------------------------------------------
#define GM 128
#define GN 64
#define KCH 128
#define NCHK (KE3 / KCH)                // 56
#define ASTR 272
#define A_BYTES (GM * ASTR)             // 34816
#define B_BYTES (GN * ASTR)             // 17408
#define STAGE (A_BYTES + B_BYTES)       // 52224
#define GEMM_SMEM (3 * STAGE)           // 156672
#define GTHR 256

struct QKVBatch {
    const __nv_bfloat16* A[3];
    const __nv_bfloat16* B[3];
    const float* br[3];
    const float* bi[3];
    __nv_bfloat16* RH[3];
    __nv_bfloat16* IH[3];
    __nv_bfloat16* RL[3];
    __nv_bfloat16* IL[3];
};

__device__ __forceinline__ int dedupA_off(int c) {
    const int bblk = c >> 3;                       // 0..6
    const int ablk = (bblk < 2) ? 0 : (bblk < 4) ? 1 : (bblk < 6) ? 2 : 3;
    return (ablk << 10) + ((c & 7) << 7);
}

__device__ __forceinline__ void gemm_mainloop_mixed(
    uint32_t sb, int tid, int m0, int n0,
    const __nv_bfloat16* A, const __nv_bfloat16* B,
    float acc[3][2][4][4])
{
    const int lane = tid & 31;
    const int wid = tid >> 5;        // 0..7
    const int wm = wid >> 1;         // 0..3 (32 rows)
    const int wn = wid & 1;          // 0..1 (32 cols)

    auto load_chunk = [&](int c, int buf) {
        const uint32_t s = sb + buf * STAGE;
        const int kcA = dedupA_off(c);
        const int kcB = c << 7;
        #pragma unroll
        for (int i = 0; i < 8; ++i) {
            const int op = tid + i * GTHR;
            const int r = op >> 4, q = op & 15;
            cpa16(s + r * ASTR + q * 16, A + (size_t)(m0 + r) * KA3 + kcA + q * 8);
        }
        #pragma unroll
        for (int i = 0; i < 4; ++i) {
            const int op = tid + i * GTHR;
            const int r = op >> 4, q = op & 15;
            cpa16(s + A_BYTES + r * ASTR + q * 16,
                  B + (size_t)(n0 + r) * KE3 + kcB + q * 8);
        }
        CPA_COMMIT();
    };

    const uint32_t aRowOff = (uint32_t)(wm * 32 + (lane & 15));
    const uint32_t aColB   = (uint32_t)((lane >> 4) * 16);
    const uint32_t bRowOff = (uint32_t)(wn * 32 + (lane & 7) + ((lane >> 4) << 3));
    const uint32_t bColB   = (uint32_t)(((lane >> 3) & 1) * 16);

    load_chunk(0, 0);
    load_chunk(1, 1);

    int c = 0;
    auto pre = [&]() {
        if (c + 1 < NCHK) CPA_WAIT(1);
        else CPA_WAIT(0);
        __syncthreads();
        // issue c+2 into buf (c+2)%3 == (c-1)%3 : all threads done reading it
        if (c + 2 < NCHK) load_chunk(c + 2, (c + 2) % 3);
    };

    // fp16 groups: acc0 (chunks 0..15), acc1 (16..31)
    #pragma unroll
    for (int g = 0; g < 2; ++g) {
        for (int cc = 0; cc < 16; ++cc) {
            pre();
            const uint32_t s = sb + (c % 3) * STAGE;
            const uint32_t aB = s + aRowOff * ASTR + aColB;
            const uint32_t bB = s + A_BYTES + bRowOff * ASTR + bColB;
            #pragma unroll
            for (int ks = 0; ks < 8; ++ks) {
                uint32_t a[2][4];
                #pragma unroll
                for (int mt = 0; mt < 2; ++mt)
                    ldsm_x4(a[mt], aB + mt * 16 * ASTR + ks * 32);
                uint32_t bf[2][4];
                #pragma unroll
                for (int np = 0; np < 2; ++np)
                    ldsm_x4(bf[np], bB + np * 16 * ASTR + ks * 32);
                #pragma unroll
                for (int mt = 0; mt < 2; ++mt)
                    #pragma unroll
                    for (int nt = 0; nt < 4; ++nt)
                        mma16816h(acc[g][mt][nt], a[mt], &bf[nt >> 1][(nt & 1) * 2]);
            }
            ++c;
        }
    }
    // bf16 group: acc2 (chunks 32..55)
    for (int cc = 0; cc < 24; ++cc) {
        pre();
        const uint32_t s = sb + (c % 3) * STAGE;
        const uint32_t aB = s + aRowOff * ASTR + aColB;
        const uint32_t bB = s + A_BYTES + bRowOff * ASTR + bColB;
        #pragma unroll
        for (int ks = 0; ks < 8; ++ks) {
            uint32_t a[2][4];
            #pragma unroll
            for (int mt = 0; mt < 2; ++mt)
                ldsm_x4(a[mt], aB + mt * 16 * ASTR + ks * 32);
            uint32_t bf[2][4];
            #pragma unroll
            for (int np = 0; np < 2; ++np)
                ldsm_x4(bf[np], bB + np * 16 * ASTR + ks * 32);
            #pragma unroll
            for (int mt = 0; mt < 2; ++mt)
                #pragma unroll
                for (int nt = 0; nt < 4; ++nt)
                    mma16816(acc[2][mt][nt], a[mt], &bf[nt >> 1][(nt & 1) * 2]);
        }
        ++c;
    }
}

#define WSCALE (1.0f / 256.0f)

// q/k/v batched GEMM: combine + write attention operands
__global__ __launch_bounds__(GTHR, 1) void gemm_qkv_kernel(QKVBatch p)
{
    extern __shared__ char smem[];
    const uint32_t sb = smem_u32(smem);
    const int tid = threadIdx.x;
    const int lane = tid & 31;
    const int wid = tid >> 5;
    const int wm = wid >> 1;
    const int wn = wid & 1;
    const int m0 = blockIdx.y * GM;
    const int n0 = blockIdx.x * GN;
    const int z = blockIdx.z;

    float acc[3][2][4][4] = {};
    gemm_mainloop_mixed(sb, tid, m0, n0, p.A[z], p.B[z], acc);

    const float* br = p.br[z];
    const float* bi = p.bi[z];
    __nv_bfloat16* RH = p.RH[z];
    __nv_bfloat16* RL = p.RL[z];
    __nv_bfloat16* IH = p.IH[z];
    __nv_bfloat16* IL = p.IL[z];

    const int rowb = m0 + wm * 32 + (lane >> 2);
    const int colb = n0 + wn * 32 + (lane & 3) * 2;
    #pragma unroll
    for (int mt = 0; mt < 2; ++mt) {
        #pragma unroll
        for (int nt = 0; nt < 4; ++nt) {
            const int col = colb + nt * 8;
            const float br0 = __ldg(&br[col]), br1 = __ldg(&br[col + 1]);
            const float bi0 = __ldg(&bi[col]), bi1 = __ldg(&bi[col + 1]);
            const int h = col >> 6, d = col & 63;
            #pragma unroll
            for (int hf = 0; hf < 2; ++hf) {
                const int row = rowb + mt * 16 + hf * 8;
                const int f = hf * 2;
                const int b = row >> 11, l = row & 2047;
                const size_t o = (((size_t)(b * Hsz + h) * Lsz) + l) * Dsz + d;
                const float p10 = acc[0][mt][nt][f] * WSCALE, p11 = acc[0][mt][nt][f+1] * WSCALE;
                const float p20 = acc[1][mt][nt][f] * WSCALE, p21 = acc[1][mt][nt][f+1] * WSCALE;
                const float p30 = acc[2][mt][nt][f],          p31 = acc[2][mt][nt][f+1];
                float yr0 = p10 - p20 + br0;
                float yr1 = p11 - p21 + br1;
                float yi0 = p30 - p10 - p20 + bi0;
                float yi1 = p31 - p11 - p21 + bi1;
                if (z == 2) {
                    *(uint32_t*)&RH[o] = packh2(yr0, yr1);
                    *(uint32_t*)&IH[o] = packh2(yi0, yi1);
                } else {
                    __nv_bfloat16 h0, l0, h1, l1;
                    split1(yr0, h0, l0); split1(yr1, h1, l1);
                    *(uint32_t*)&RH[o] = packbf2(h0, h1);
                    *(uint32_t*)&RL[o] = packbf2(l0, l1);
                    split1(yi0, h0, l0); split1(yi1, h1, l1);
                    *(uint32_t*)&IH[o] = packbf2(h0, h1);
                    *(uint32_t*)&IL[o] = packbf2(l0, l1);
                }
            }
        }
    }
}

// output-layer GEMM: combine, fp32 epilogue to [B,L,E]
__global__ __launch_bounds__(GTHR, 1) void gemm_kernel(
    const __nv_bfloat16* __restrict__ A,
    const __nv_bfloat16* __restrict__ B,
    const float* __restrict__ br, const float* __restrict__ bi,
    float* __restrict__ Yr, float* __restrict__ Yi)
{
    extern __shared__ char smem[];
    const uint32_t sb = smem_u32(smem);
    const int tid = threadIdx.x;
    const int lane = tid & 31;
    const int wid = tid >> 5;
    const int wm = wid >> 1;
    const int wn = wid & 1;
    const int m0 = blockIdx.y * GM;
    const int n0 = blockIdx.x * GN;

    float acc[3][2][4][4] = {};
    gemm_mainloop_mixed(sb, tid, m0, n0, A, B, acc);

    const int rowb = m0 + wm * 32 + (lane >> 2);
    const int colb = n0 + wn * 32 + (lane & 3) * 2;
    #pragma unroll
    for (int mt = 0; mt < 2; ++mt) {
        #pragma unroll
        for (int nt = 0; nt < 4; ++nt) {
            const int col = colb + nt * 8;
            const float br0 = __ldg(&br[col]), br1 = __ldg(&br[col + 1]);
            const float bi0 = __ldg(&bi[col]), bi1 = __ldg(&bi[col + 1]);
            #pragma unroll
            for (int hf = 0; hf < 2; ++hf) {
                const int row = rowb + mt * 16 + hf * 8;
                const int f = hf * 2;
                const float p10 = acc[0][mt][nt][f] * WSCALE, p11 = acc[0][mt][nt][f+1] * WSCALE;
                const float p20 = acc[1][mt][nt][f] * WSCALE, p21 = acc[1][mt][nt][f+1] * WSCALE;
                const float p30 = acc[2][mt][nt][f],          p31 = acc[2][mt][nt][f+1];
                float2 v;
                v.x = p10 - p20 + br0;
                v.y = p11 - p21 + br1;
                *(float2*)&Yr[(size_t)row * Esz + col] = v;
                v.x = p30 - p10 - p20 + bi0;
                v.y = p31 - p11 - p21 + bi1;
                *(float2*)&Yi[(size_t)row * Esz + col] = v;
            }
        }
    }
}

// ---------------------------------------------------------------------------
// Tensor-core flash attention (round-11 design, at its mma floor). Epilogue
// writes the o-layer dedup A_cat (4 blocks, width KA3).
// ---------------------------------------------------------------------------
#define AT_STR 144
#define AT_MAT (64 * AT_STR)
#define AT_QMAT (128 * AT_STR)
#define AT_QBYTES (4 * AT_QMAT)              // 73728
#define AT_STAGE (6 * AT_MAT)                // 55296
#define AT_SMEM (AT_QBYTES + 2 * AT_STAGE)   // 184320
#define NKT (Lsz / 64)

__global__ __launch_bounds__(256, 1) void attn_tc_kernel(
    const __nv_bfloat16* __restrict__ QRH, const __nv_bfloat16* __restrict__ QRL,
    const __nv_bfloat16* __restrict__ QIH, const __nv_bfloat16* __restrict__ QIL,
    const __nv_bfloat16* __restrict__ KRH, const __nv_bfloat16* __restrict__ KRL,
    const __nv_bfloat16* __restrict__ KIH, const __nv_bfloat16* __restrict__ KIL,
    const __half* __restrict__ VRH, const __half* __restrict__ VIH,
    __nv_bfloat16* __restrict__ Ao)
{
    extern __shared__ char smem[];
    const uint32_t sb = smem_u32(smem);
    const int tid = threadIdx.x;
    const int lane = tid & 31;
    const int wid = tid >> 5;
    const int q0 = blockIdx.x * 128;
    const int bh = blockIdx.y;
    const size_t pb = (size_t)bh * Lsz * Dsz;

    const __nv_bfloat16* Qm[4] = {QRH + pb, QRL + pb, QIH + pb, QIL + pb};
    const void* Km[6] = {KRH + pb, KRL + pb, KIH + pb, KIL + pb,
                         VRH + pb, VIH + pb};

    #pragma unroll
    for (int mat = 0; mat < 4; ++mat) {
        #pragma unroll
        for (int i = 0; i < 4; ++i) {
            const int op = tid + i * 256;
            const int r = op >> 3, q = op & 7;
            cpa16(sb + mat * AT_QMAT + r * AT_STR + q * 16,
                  Qm[mat] + (size_t)(q0 + r) * Dsz + q * 8);
        }
    }
    CPA_COMMIT();

    auto issue_kv = [&](int kt, int buf) {
        const uint32_t base = sb + AT_QBYTES + buf * AT_STAGE;
        #pragma unroll
        for (int mat = 0; mat < 6; ++mat) {
            #pragma unroll
            for (int i = 0; i < 2; ++i) {
                const int op = tid + i * 256;
                const int r = op >> 3, q = op & 7;
                cpa16(base + mat * AT_MAT + r * AT_STR + q * 16,
                      (const char*)Km[mat] + ((size_t)(kt * 64 + r) * Dsz + q * 8) * 2);
            }
        }
        CPA_COMMIT();
    };

    issue_kv(0, 0);
    CPA_WAIT(0);
    __syncthreads();

    float oR[8][4] = {};
    float oI[8][4] = {};
    float mrun0 = -INFINITY, mrun1 = -INFINITY;
    float lrun0 = 0.f, lrun1 = 0.f;
    const float sc = 0.125f * 1.4426950408889634f;

    const uint32_t aoff = (uint32_t)((wid * 16 + (lane & 15)) * AT_STR + (lane >> 4) * 16);
    const uint32_t boff = (uint32_t)(((lane & 7) + ((lane >> 4) << 3)) * AT_STR
                                     + ((lane >> 3) & 1) * 16);
    const uint32_t voff = (uint32_t)((lane & 15) * AT_STR + (lane >> 4) * 16);

    for (int kt = 0; kt < NKT; ++kt) {
        if (kt + 1 < NKT) { issue_kv(kt + 1, (kt + 1) & 1); CPA_WAIT(1); }
        else CPA_WAIT(0);
        __syncthreads();
        const uint32_t kb = sb + AT_QBYTES + (kt & 1) * AT_STAGE;

        // ---- scores: 6 bf16 hi/lo chains ----
        float sacc[8][4] = {};
        #pragma unroll
        for (int ks = 0; ks < 4; ++ks) {
            uint32_t aq[4][4];
            #pragma unroll
            for (int m = 0; m < 4; ++m)
                ldsm_x4(aq[m], sb + m * AT_QMAT + aoff + ks * 32);
            #pragma unroll
            for (int np = 0; np < 4; ++np) {
                uint32_t kf[4][4];
                #pragma unroll
                for (int m = 0; m < 4; ++m)
                    ldsm_x4(kf[m], kb + m * AT_MAT + boff + np * 16 * AT_STR + ks * 32);
                mma16816(sacc[2*np],   aq[0], &kf[0][0]);
                mma16816(sacc[2*np+1], aq[0], &kf[0][2]);
                mma16816(sacc[2*np],   aq[0], &kf[1][0]);
                mma16816(sacc[2*np+1], aq[0], &kf[1][2]);
                mma16816(sacc[2*np],   aq[1], &kf[0][0]);
                mma16816(sacc[2*np+1], aq[1], &kf[0][2]);
                mma16816(sacc[2*np],   aq[2], &kf[2][0]);
                mma16816(sacc[2*np+1], aq[2], &kf[2][2]);
                mma16816(sacc[2*np],   aq[2], &kf[3][0]);
                mma16816(sacc[2*np+1], aq[2], &kf[3][2]);
                mma16816(sacc[2*np],   aq[3], &kf[2][0]);
                mma16816(sacc[2*np+1], aq[3], &kf[2][2]);
            }
        }

        // ---- online softmax, P -> fp16 ----
        float mt0 = -INFINITY, mt1 = -INFINITY;
        #pragma unroll
        for (int j = 0; j < 8; ++j) {
            mt0 = fmaxf(mt0, fmaxf(sacc[j][0], sacc[j][1]));
            mt1 = fmaxf(mt1, fmaxf(sacc[j][2], sacc[j][3]));
        }
        mt0 = fmaxf(mt0, __shfl_xor_sync(0xffffffffu, mt0, 1));
        mt0 = fmaxf(mt0, __shfl_xor_sync(0xffffffffu, mt0, 2));
        mt1 = fmaxf(mt1, __shfl_xor_sync(0xffffffffu, mt1, 1));
        mt1 = fmaxf(mt1, __shfl_xor_sync(0xffffffffu, mt1, 2));
        const float mn0 = fmaxf(mrun0, mt0 * sc);
        const float mn1 = fmaxf(mrun1, mt1 * sc);

        float rs0 = 0.f, rs1 = 0.f;
        uint32_t ph[4][4];
        #pragma unroll
        for (int j = 0; j < 8; ++j) {
            float p0 = fexp2(fmaf(sacc[j][0], sc, -mn0));
            float p1 = fexp2(fmaf(sacc[j][1], sc, -mn0));
            float p2 = fexp2(fmaf(sacc[j][2], sc, -mn1));
            float p3 = fexp2(fmaf(sacc[j][3], sc, -mn1));
            rs0 += p0 + p1;
            rs1 += p2 + p3;
            const int ks = j >> 1;
            const int hx = (j & 1) * 2;
            ph[ks][hx + 0] = packh2(p0, p1);
            ph[ks][hx + 1] = packh2(p2, p3);
        }

        rs0 += __shfl_xor_sync(0xffffffffu, rs0, 1);
        rs0 += __shfl_xor_sync(0xffffffffu, rs0, 2);
        rs1 += __shfl_xor_sync(0xffffffffu, rs1, 1);
        rs1 += __shfl_xor_sync(0xffffffffu, rs1, 2);
        const float c0 = fexp2(mrun0 - mn0);
        const float c1 = fexp2(mrun1 - mn1);
        lrun0 = lrun0 * c0 + rs0;
        lrun1 = lrun1 * c1 + rs1;
        mrun0 = mn0; mrun1 = mn1;
        #pragma unroll
        for (int j = 0; j < 8; ++j) {
            oR[j][0] *= c0; oR[j][1] *= c0; oR[j][2] *= c1; oR[j][3] *= c1;
            oI[j][0] *= c0; oI[j][1] *= c0; oI[j][2] *= c1; oI[j][3] *= c1;
        }

        // ---- O += P @ V : 2 fp16 chains ----
        #pragma unroll
        for (int ks = 0; ks < 4; ++ks) {
            #pragma unroll
            for (int np = 0; np < 4; ++np) {
                uint32_t vr[4], vi[4];
                ldsm_x4_t(vr, kb + 4 * AT_MAT + voff + ks * 16 * AT_STR + np * 32);
                ldsm_x4_t(vi, kb + 5 * AT_MAT + voff + ks * 16 * AT_STR + np * 32);
                mma16816h(oR[2*np],   ph[ks], &vr[0]);
                mma16816h(oR[2*np+1], ph[ks], &vr[2]);
                mma16816h(oI[2*np],   ph[ks], &vi[0]);
                mma16816h(oI[2*np+1], ph[ks], &vi[2]);
            }
        }
        __syncthreads();
    }

    // finalize: write o-layer dedup A_cat (4 blocks, width KA3)
    const float inv0 = 1.0f / lrun0;
    const float inv1 = 1.0f / lrun1;
    const int b = bh >> 4, h = bh & 15;
    const int row0 = q0 + wid * 16 + (lane >> 2);
    #pragma unroll
    for (int j = 0; j < 8; ++j) {
        const int e = h * 64 + j * 8 + (lane & 3) * 2;
        #pragma unroll
        for (int hf = 0; hf < 2; ++hf) {
            const int l = row0 + hf * 8;
            const float inv = (hf == 0) ? inv0 : inv1;
            const int f = hf * 2;
            const float yr0 = oR[j][f] * inv,  yr1 = oR[j][f+1] * inv;
            const float yi0 = oI[j][f] * inv,  yi1 = oI[j][f+1] * inv;
            const float ys0 = yr0 + yi0, ys1 = yr1 + yi1;
            __nv_bfloat16* base = Ao + (size_t)(b * Lsz + l) * KA3 + e;
            __nv_bfloat16 h0, l0, h1, l1;
            split1(ys0, h0, l0); split1(ys1, h1, l1);
            *(uint32_t*)(base + 0)    = packh2(yr0, yr1);
            *(uint32_t*)(base + 1024) = packh2(yi0, yi1);
            *(uint32_t*)(base + 2048) = packbf2(h0, h1);
            *(uint32_t*)(base + 3072) = packbf2(l0, l1);
        }
    }
}

// ---------------------------------------------------------------------------
extern "C" void kernel_launch(void* const* d_in, const int* in_sizes, int n_in,
                              void* d_out, int out_size)
{
    (void)in_sizes; (void)n_in; (void)out_size;
    const float* query_r = (const float*)d_in[0];
    const float* query_i = (const float*)d_in[1];
    const float* key_r   = (const float*)d_in[2];
    const float* key_i   = (const float*)d_in[3];
    const float* value_r = (const float*)d_in[4];
    const float* value_i = (const float*)d_in[5];
    const float* Wq_r = (const float*)d_in[6];
    const float* Wq_i = (const float*)d_in[7];
    const float* bq_r = (const float*)d_in[8];
    const float* bq_i = (const float*)d_in[9];
    const float* Wk_r = (const float*)d_in[10];
    const float* Wk_i = (const float*)d_in[11];
    const float* bk_r = (const float*)d_in[12];
    const float* bk_i = (const float*)d_in[13];
    const float* Wv_r = (const float*)d_in[14];
    const float* Wv_i = (const float*)d_in[15];
    const float* bv_r = (const float*)d_in[16];
    const float* bv_i = (const float*)d_in[17];
    const float* Wo_r = (const float*)d_in[18];
    const float* Wo_i = (const float*)d_in[19];
    const float* bo_r = (const float*)d_in[20];
    const float* bo_i = (const float*)d_in[21];

    __nv_bfloat16* acat = nullptr;
    cudaGetSymbolAddress((void**)&acat, g_acat);
    __nv_bfloat16* bcat = nullptr;
    cudaGetSymbolAddress((void**)&bcat, g_bcat);
    __nv_bfloat16* attn = nullptr;
    cudaGetSymbolAddress((void**)&attn, g_attn);

    auto Wc = [&](int s) { return bcat + (size_t)s * Esz * KE3; };
    auto Ac = [&](int s) { return acat + (size_t)s * NROW * KA3; };
    auto At = [&](int s) { return attn + (size_t)s * BHD; };

    SplitWBatch wb;
    wb.Wr[0] = Wq_r; wb.Wi[0] = Wq_i; wb.B[0] = Wc(0);
    wb.Wr[1] = Wk_r; wb.Wi[1] = Wk_i; wb.B[1] = Wc(1);
    wb.Wr[2] = Wv_r; wb.Wi[2] = Wv_i; wb.B[2] = Wc(2);
    wb.Wr[3] = Wo_r; wb.Wi[3] = Wo_i; wb.B[3] = Wc(3);
    splitW_kernel<<<dim3(256, 1, 4), 256>>>(wb);

    SplitABatch ab;
    ab.Xr[0] = query_r; ab.Xi[0] = query_i; ab.A[0] = Ac(0);
    ab.Xr[1] = key_r;   ab.Xi[1] = key_i;   ab.A[1] = Ac(1);
    ab.Xr[2] = value_r; ab.Xi[2] = value_i; ab.A[2] = Ac(2);
    splitA_kernel<<<dim3(384, 1, 3), 256>>>(ab);

    QKVBatch batch;
    batch.A[0] = Ac(0); batch.A[1] = Ac(1); batch.A[2] = Ac(2);
    batch.B[0] = Wc(0); batch.B[1] = Wc(1); batch.B[2] = Wc(2);
    batch.br[0] = bq_r; batch.bi[0] = bq_i;
    batch.br[1] = bk_r; batch.bi[1] = bk_i;
    batch.br[2] = bv_r; batch.bi[2] = bv_i;
    batch.RH[0] = At(0); batch.RL[0] = At(1); batch.IH[0] = At(2); batch.IL[0] = At(3);
    batch.RH[1] = At(4); batch.RL[1] = At(5); batch.IH[1] = At(6); batch.IL[1] = At(7);
    batch.RH[2] = At(8); batch.IH[2] = At(9); batch.RL[2] = At(8); batch.IL[2] = At(9);

    cudaFuncSetAttribute((const void*)gemm_qkv_kernel,
                         cudaFuncAttributeMaxDynamicSharedMemorySize, GEMM_SMEM);
    cudaFuncSetAttribute((const void*)gemm_kernel,
                         cudaFuncAttributeMaxDynamicSharedMemorySize, GEMM_SMEM);

    gemm_qkv_kernel<<<dim3(Esz / GN, NROW / GM, 3), GTHR, GEMM_SMEM>>>(batch);

    cudaFuncSetAttribute((const void*)attn_tc_kernel,
                         cudaFuncAttributeMaxDynamicSharedMemorySize, AT_SMEM);
    attn_tc_kernel<<<dim3(Lsz / 128, Bsz * Hsz), 256, AT_SMEM>>>(
        At(0), At(1), At(2), At(3), At(4), At(5), At(6), At(7),
        (const __half*)At(8), (const __half*)At(9), Ac(0));

    float* yr = (float*)d_out;
    float* yi = yr + BLE;
    gemm_kernel<<<dim3(Esz / GN, NROW / GM), GTHR, GEMM_SMEM>>>(
        Ac(0), Wc(3), bo_r, bo_i, yr, yi);
}

// round 17
// speedup vs baseline: 1.1328x; 1.1328x over previous
#include <cuda_runtime.h>
#include <cuda_bf16.h>
#include <cuda_fp16.h>
#include <math.h>
#include <cstdint>

#define Bsz 2
#define Lsz 2048
#define Esz 1024
#define Hsz 16
#define Dsz 64
#define NROW 4096               // Bsz*Lsz
#define BLE  (Bsz*Lsz*Esz)      // 4,194,304
#define KE3  7168               // B width: 7 blocks
#define KA3  4096               // A width: 4 dedup blocks [Xr16|Xi16|Sh|Sl]
#define BHD  ((size_t)Bsz*Hsz*Lsz*Dsz)

// A (dedup): [Xr16 | Xi16 | Sh | Sl]  (fp16, fp16, bf16, bf16), S = Xr+Xi
// B: [W'rh W'rl | W'ih W'il | Wsh Wsl Wsh] (fp16 W'=W*256; bf16 Ws=Wr+Wi)
// acc0 = Xr·W'r (fp16), acc1 = Xi·W'i (fp16), acc2 = S·Ws (bf16)
// B-block -> A-block pairing: {0,0,1,1,2,2,3}
// Yr = (acc0-acc1)/256 + br ; Yi = acc2 - (acc0+acc1)/256 + bi
__device__ __nv_bfloat16 g_acat[3ull * NROW * KA3];           // 100 MB
__device__ __nv_bfloat16 g_bcat[4ull * Esz * KE3];            // 58.7 MB
// attention arrays: q(rh,rl,ih,il) k(4) bf16 ; v(rh,ih) fp16
__device__ __nv_bfloat16 g_attn[10ull * BHD];                 // 80 MB

// ---------------------------------------------------------------------------
// helpers
// ---------------------------------------------------------------------------
__device__ __forceinline__ uint32_t smem_u32(const void* p) {
    uint32_t a;
    asm("{ .reg .u64 t; cvta.to.shared.u64 t, %1; cvt.u32.u64 %0, t; }" : "=r"(a) : "l"(p));
    return a;
}
__device__ __forceinline__ void cpa16(uint32_t dst, const void* src) {
    asm volatile("cp.async.cg.shared.global [%0], [%1], 16;" :: "r"(dst), "l"(src));
}
#define CPA_COMMIT() asm volatile("cp.async.commit_group;" ::: "memory")
#define CPA_WAIT(n)  asm volatile("cp.async.wait_group %0;" :: "n"(n) : "memory")

__device__ __forceinline__ void ldsm_x4(uint32_t* r, uint32_t addr) {
    asm volatile("ldmatrix.sync.aligned.m8n8.x4.shared.b16 {%0,%1,%2,%3}, [%4];"
        : "=r"(r[0]), "=r"(r[1]), "=r"(r[2]), "=r"(r[3]) : "r"(addr));
}
__device__ __forceinline__ void ldsm_x4_t(uint32_t* r, uint32_t addr) {
    asm volatile("ldmatrix.sync.aligned.m8n8.x4.trans.shared.b16 {%0,%1,%2,%3}, [%4];"
        : "=r"(r[0]), "=r"(r[1]), "=r"(r[2]), "=r"(r[3]) : "r"(addr));
}
__device__ __forceinline__ void mma16816(float* c, const uint32_t* a, const uint32_t* b) {
    asm volatile("mma.sync.aligned.m16n8k16.row.col.f32.bf16.bf16.f32 "
        "{%0,%1,%2,%3}, {%4,%5,%6,%7}, {%8,%9}, {%0,%1,%2,%3};"
        : "+f"(c[0]), "+f"(c[1]), "+f"(c[2]), "+f"(c[3])
        : "r"(a[0]), "r"(a[1]), "r"(a[2]), "r"(a[3]), "r"(b[0]), "r"(b[1]));
}
__device__ __forceinline__ void mma16816h(float* c, const uint32_t* a, const uint32_t* b) {
    asm volatile("mma.sync.aligned.m16n8k16.row.col.f32.f16.f16.f32 "
        "{%0,%1,%2,%3}, {%4,%5,%6,%7}, {%8,%9}, {%0,%1,%2,%3};"
        : "+f"(c[0]), "+f"(c[1]), "+f"(c[2]), "+f"(c[3])
        : "r"(a[0]), "r"(a[1]), "r"(a[2]), "r"(a[3]), "r"(b[0]), "r"(b[1]));
}
__device__ __forceinline__ float fexp2(float x) {
    float y;
    asm("ex2.approx.ftz.f32 %0, %1;" : "=f"(y) : "f"(x));
    return y;
}
__device__ __forceinline__ void split1(float x, __nv_bfloat16& h, __nv_bfloat16& l) {
    h = __float2bfloat16(x);
    l = __float2bfloat16(x - __bfloat162float(h));
}
__device__ __forceinline__ void h2split(float v, __half& h, __half& l) {
    h = __float2half(v);
    l = __float2half(v - __half2float(h));
}
__device__ __forceinline__ uint32_t packbf2(__nv_bfloat16 a, __nv_bfloat16 b) {
    __nv_bfloat162 t; t.x = a; t.y = b;
    return *(uint32_t*)&t;
}
__device__ __forceinline__ uint32_t packh2(float a, float b) {
    __half2 t = __floats2half2_rn(a, b);
    return *(uint32_t*)&t;
}
__device__ __forceinline__ uint32_t packhh(__half a, __half b) {
    __half2 t; t.x = a; t.y = b;
    return *(uint32_t*)&t;
}

// ---------------------------------------------------------------------------
// fused split kernels (z-batched)
// ---------------------------------------------------------------------------
struct SplitABatch { const float* Xr[3]; const float* Xi[3]; __nv_bfloat16* A[3]; };
struct SplitWBatch { const float* Wr[4]; const float* Wi[4]; __nv_bfloat16* B[4]; };

__global__ __launch_bounds__(256) void splitA_kernel(SplitABatch p)
{
    const int z = blockIdx.z;
    const float* __restrict__ Xr = p.Xr[z];
    const float* __restrict__ Xi = p.Xi[z];
    __nv_bfloat16* __restrict__ A = p.A[z];
    const int total = NROW * Esz / 4;
    int idx = blockIdx.x * 256 + threadIdx.x;
    const int stride = gridDim.x * 256;
    for (; idx < total; idx += stride) {
        const int m = idx >> 8;
        const int kq = (idx & 255) << 2;
        float4 xr = ((const float4*)Xr)[idx];
        float4 xi = ((const float4*)Xi)[idx];
        uint2 r16 = make_uint2(packh2(xr.x, xr.y), packh2(xr.z, xr.w));
        uint2 i16 = make_uint2(packh2(xi.x, xi.y), packh2(xi.z, xi.w));
        __nv_bfloat16 sh[4], sl[4];
        split1(xr.x + xi.x, sh[0], sl[0]); split1(xr.y + xi.y, sh[1], sl[1]);
        split1(xr.z + xi.z, sh[2], sl[2]); split1(xr.w + xi.w, sh[3], sl[3]);
        __nv_bfloat16* base = A + (size_t)m * KA3 + kq;
        *(uint2*)(base + 0)    = r16;
        *(uint2*)(base + 1024) = i16;
        *(uint2*)(base + 2048) = make_uint2(packbf2(sh[0], sh[1]), packbf2(sh[2], sh[3]));
        *(uint2*)(base + 3072) = make_uint2(packbf2(sl[0], sl[1]), packbf2(sl[2], sl[3]));
    }
}

__global__ __launch_bounds__(256) void splitW_kernel(SplitWBatch p)
{
    const int z = blockIdx.z;
    const float* __restrict__ Wr = p.Wr[z];
    const float* __restrict__ Wi = p.Wi[z];
    __nv_bfloat16* __restrict__ B = p.B[z];
    const int total = Esz * Esz / 4;
    int idx = blockIdx.x * 256 + threadIdx.x;
    const int stride = gridDim.x * 256;
    for (; idx < total; idx += stride) {
        const int n = idx >> 8;
        const int kq = (idx & 255) << 2;
        float4 wr = ((const float4*)Wr)[idx];
        float4 wi = ((const float4*)Wi)[idx];
        __half rh[4], rl[4], ih[4], il[4];
        h2split(wr.x * 256.f, rh[0], rl[0]); h2split(wr.y * 256.f, rh[1], rl[1]);
        h2split(wr.z * 256.f, rh[2], rl[2]); h2split(wr.w * 256.f, rh[3], rl[3]);
        h2split(wi.x * 256.f, ih[0], il[0]); h2split(wi.y * 256.f, ih[1], il[1]);
        h2split(wi.z * 256.f, ih[2], il[2]); h2split(wi.w * 256.f, ih[3], il[3]);
        __nv_bfloat16 sh[4], sl[4];
        split1(wr.x + wi.x, sh[0], sl[0]); split1(wr.y + wi.y, sh[1], sl[1]);
        split1(wr.z + wi.z, sh[2], sl[2]); split1(wr.w + wi.w, sh[3], sl[3]);
        __nv_bfloat16* b = B + (size_t)n * KE3 + kq;
        *(uint2*)(b + 0)    = make_uint2(packhh(rh[0], rh[1]), packhh(rh[2], rh[3]));
        *(uint2*)(b + 1024) = make_uint2(packhh(rl[0], rl[1]), packhh(rl[2], rl[3]));
        *(uint2*)(b + 2048) = make_uint2(packhh(ih[0], ih[1]), packhh(ih[2], ih[3]));
        *(uint2*)(b + 3072) = make_uint2(packhh(il[0], il[1]), packhh(il[2], il[3]));
        uint2 shv = make_uint2(packbf2(sh[0], sh[1]), packbf2(sh[2], sh[3]));
        uint2 slv = make_uint2(packbf2(sl[0], sl[1]), packbf2(sl[2], sl[3]));
        *(uint2*)(b + 4096) = shv;
        *(uint2*)(b + 5120) = slv;
        *(uint2*)(b + 6144) = shv;
    }
}

// ---------------------------------------------------------------------------
// Mixed Karatsuba GEMM. CTA 128x64, 256 threads (8 warps, 4m x 2n, warp 32x32),
// TWO CTAs per SM (2-buffer ring, 104KB smem, regs capped at 128).
// KCH=128 (8 k-steps/chunk), NCHK=56, single sync per chunk.
// chunk groups: acc0 fp16 (0-15), acc1 fp16 (16-31), acc2 bf16 (32-55).
// A dedup: per B-block map {0,0,1,1,2,2,3}.
// ---------------------------------------------------------------------------
#define GM 128
#define GN 64
#define KCH 128
#define NCHK (KE3 / KCH)                // 56
#define ASTR 272
#define A_BYTES (GM * ASTR)             // 34816
#define B_BYTES (GN * ASTR)             // 17408
#define STAGE (A_BYTES + B_BYTES)       // 52224
#define GEMM_SMEM (2 * STAGE)           // 104448  -> 2 CTAs/SM
#define GTHR 256

struct QKVBatch {
    const __nv_bfloat16* A[3];
    const __nv_bfloat16* B[3];
    const float* br[3];
    const float* bi[3];
    __nv_bfloat16* RH[3];
    __nv_bfloat16* IH[3];
    __nv_bfloat16* RL[3];
    __nv_bfloat16* IL[3];
};

__device__ __forceinline__ int dedupA_off(int c) {
    const int bblk = c >> 3;                       // 0..6
    const int ablk = (bblk < 2) ? 0 : (bblk < 4) ? 1 : (bblk < 6) ? 2 : 3;
    return (ablk << 10) + ((c & 7) << 7);
}

__device__ __forceinline__ void gemm_mainloop_mixed(
    uint32_t sb, int tid, int m0, int n0,
    const __nv_bfloat16* A, const __nv_bfloat16* B,
    float acc[3][2][4][4])
{
    const int lane = tid & 31;
    const int wid = tid >> 5;        // 0..7
    const int wm = wid >> 1;         // 0..3 (32 rows)
    const int wn = wid & 1;          // 0..1 (32 cols)

    auto load_chunk = [&](int c, int buf) {
        const uint32_t s = sb + buf * STAGE;
        const int kcA = dedupA_off(c);
        const int kcB = c << 7;
        #pragma unroll
        for (int i = 0; i < 8; ++i) {
            const int op = tid + i * GTHR;
            const int r = op >> 4, q = op & 15;
            cpa16(s + r * ASTR + q * 16, A + (size_t)(m0 + r) * KA3 + kcA + q * 8);
        }
        #pragma unroll
        for (int i = 0; i < 4; ++i) {
            const int op = tid + i * GTHR;
            const int r = op >> 4, q = op & 15;
            cpa16(s + A_BYTES + r * ASTR + q * 16,
                  B + (size_t)(n0 + r) * KE3 + kcB + q * 8);
        }
        CPA_COMMIT();
    };

    const uint32_t aRowOff = (uint32_t)(wm * 32 + (lane & 15));
    const uint32_t aColB   = (uint32_t)((lane >> 4) * 16);
    const uint32_t bRowOff = (uint32_t)(wn * 32 + (lane & 7) + ((lane >> 4) << 3));
    const uint32_t bColB   = (uint32_t)(((lane >> 3) & 1) * 16);

    load_chunk(0, 0);

    int c = 0;
    // 2-buffer ring, one sync per chunk:
    //  wait(0): chunk c resident. sync: all reads of buf(c-1) done CTA-wide.
    //  issue c+1 into buf (c+1)&1 == buf (c-1)&1 (now free); overlaps compute of c.
    auto pre = [&]() {
        CPA_WAIT(0);
        __syncthreads();
        if (c + 1 < NCHK) load_chunk(c + 1, (c + 1) & 1);
    };

    // fp16 groups: acc0 (chunks 0..15), acc1 (16..31)
    #pragma unroll
    for (int g = 0; g < 2; ++g) {
        for (int cc = 0; cc < 16; ++cc) {
            pre();
            const uint32_t s = sb + (c & 1) * STAGE;
            const uint32_t aB = s + aRowOff * ASTR + aColB;
            const uint32_t bB = s + A_BYTES + bRowOff * ASTR + bColB;
            #pragma unroll
            for (int ks = 0; ks < 8; ++ks) {
                uint32_t a[2][4];
                #pragma unroll
                for (int mt = 0; mt < 2; ++mt)
                    ldsm_x4(a[mt], aB + mt * 16 * ASTR + ks * 32);
                uint32_t bf[2][4];
                #pragma unroll
                for (int np = 0; np < 2; ++np)
                    ldsm_x4(bf[np], bB + np * 16 * ASTR + ks * 32);
                #pragma unroll
                for (int mt = 0; mt < 2; ++mt)
                    #pragma unroll
                    for (int nt = 0; nt < 4; ++nt)
                        mma16816h(acc[g][mt][nt], a[mt], &bf[nt >> 1][(nt & 1) * 2]);
            }
            ++c;
        }
    }
    // bf16 group: acc2 (chunks 32..55)
    for (int cc = 0; cc < 24; ++cc) {
        pre();
        const uint32_t s = sb + (c & 1) * STAGE;
        const uint32_t aB = s + aRowOff * ASTR + aColB;
        const uint32_t bB = s + A_BYTES + bRowOff * ASTR + bColB;
        #pragma unroll
        for (int ks = 0; ks < 8; ++ks) {
            uint32_t a[2][4];
            #pragma unroll
            for (int mt = 0; mt < 2; ++mt)
                ldsm_x4(a[mt], aB + mt * 16 * ASTR + ks * 32);
            uint32_t bf[2][4];
            #pragma unroll
            for (int np = 0; np < 2; ++np)
                ldsm_x4(bf[np], bB + np * 16 * ASTR + ks * 32);
            #pragma unroll
            for (int mt = 0; mt < 2; ++mt)
                #pragma unroll
                for (int nt = 0; nt < 4; ++nt)
                    mma16816(acc[2][mt][nt], a[mt], &bf[nt >> 1][(nt & 1) * 2]);
        }
        ++c;
    }
}

#define WSCALE (1.0f / 256.0f)

// q/k/v batched GEMM: combine + write attention operands
__global__ __launch_bounds__(GTHR, 2) void gemm_qkv_kernel(QKVBatch p)
{
    extern __shared__ char smem[];
    const uint32_t sb = smem_u32(smem);
    const int tid = threadIdx.x;
    const int lane = tid & 31;
    const int wid = tid >> 5;
    const int wm = wid >> 1;
    const int wn = wid & 1;
    const int m0 = blockIdx.y * GM;
    const int n0 = blockIdx.x * GN;
    const int z = blockIdx.z;

    float acc[3][2][4][4] = {};
    gemm_mainloop_mixed(sb, tid, m0, n0, p.A[z], p.B[z], acc);

    const float* br = p.br[z];
    const float* bi = p.bi[z];
    __nv_bfloat16* RH = p.RH[z];
    __nv_bfloat16* RL = p.RL[z];
    __nv_bfloat16* IH = p.IH[z];
    __nv_bfloat16* IL = p.IL[z];

    const int rowb = m0 + wm * 32 + (lane >> 2);
    const int colb = n0 + wn * 32 + (lane & 3) * 2;
    #pragma unroll
    for (int mt = 0; mt < 2; ++mt) {
        #pragma unroll
        for (int nt = 0; nt < 4; ++nt) {
            const int col = colb + nt * 8;
            const float br0 = __ldg(&br[col]), br1 = __ldg(&br[col + 1]);
            const float bi0 = __ldg(&bi[col]), bi1 = __ldg(&bi[col + 1]);
            const int h = col >> 6, d = col & 63;
            #pragma unroll
            for (int hf = 0; hf < 2; ++hf) {
                const int row = rowb + mt * 16 + hf * 8;
                const int f = hf * 2;
                const int b = row >> 11, l = row & 2047;
                const size_t o = (((size_t)(b * Hsz + h) * Lsz) + l) * Dsz + d;
                const float p10 = acc[0][mt][nt][f] * WSCALE, p11 = acc[0][mt][nt][f+1] * WSCALE;
                const float p20 = acc[1][mt][nt][f] * WSCALE, p21 = acc[1][mt][nt][f+1] * WSCALE;
                const float p30 = acc[2][mt][nt][f],          p31 = acc[2][mt][nt][f+1];
                float yr0 = p10 - p20 + br0;
                float yr1 = p11 - p21 + br1;
                float yi0 = p30 - p10 - p20 + bi0;
                float yi1 = p31 - p11 - p21 + bi1;
                if (z == 2) {
                    *(uint32_t*)&RH[o] = packh2(yr0, yr1);
                    *(uint32_t*)&IH[o] = packh2(yi0, yi1);
                } else {
                    __nv_bfloat16 h0, l0, h1, l1;
                    split1(yr0, h0, l0); split1(yr1, h1, l1);
                    *(uint32_t*)&RH[o] = packbf2(h0, h1);
                    *(uint32_t*)&RL[o] = packbf2(l0, l1);
                    split1(yi0, h0, l0); split1(yi1, h1, l1);
                    *(uint32_t*)&IH[o] = packbf2(h0, h1);
                    *(uint32_t*)&IL[o] = packbf2(l0, l1);
                }
            }
        }
    }
}

// output-layer GEMM: combine, fp32 epilogue to [B,L,E]
__global__ __launch_bounds__(GTHR, 2) void gemm_kernel(
    const __nv_bfloat16* __restrict__ A,
    const __nv_bfloat16* __restrict__ B,
    const float* __restrict__ br, const float* __restrict__ bi,
    float* __restrict__ Yr, float* __restrict__ Yi)
{
    extern __shared__ char smem[];
    const uint32_t sb = smem_u32(smem);
    const int tid = threadIdx.x;
    const int lane = tid & 31;
    const int wid = tid >> 5;
    const int wm = wid >> 1;
    const int wn = wid & 1;
    const int m0 = blockIdx.y * GM;
    const int n0 = blockIdx.x * GN;

    float acc[3][2][4][4] = {};
    gemm_mainloop_mixed(sb, tid, m0, n0, A, B, acc);

    const int rowb = m0 + wm * 32 + (lane >> 2);
    const int colb = n0 + wn * 32 + (lane & 3) * 2;
    #pragma unroll
    for (int mt = 0; mt < 2; ++mt) {
        #pragma unroll
        for (int nt = 0; nt < 4; ++nt) {
            const int col = colb + nt * 8;
            const float br0 = __ldg(&br[col]), br1 = __ldg(&br[col + 1]);
            const float bi0 = __ldg(&bi[col]), bi1 = __ldg(&bi[col + 1]);
            #pragma unroll
            for (int hf = 0; hf < 2; ++hf) {
                const int row = rowb + mt * 16 + hf * 8;
                const int f = hf * 2;
                const float p10 = acc[0][mt][nt][f] * WSCALE, p11 = acc[0][mt][nt][f+1] * WSCALE;
                const float p20 = acc[1][mt][nt][f] * WSCALE, p21 = acc[1][mt][nt][f+1] * WSCALE;
                const float p30 = acc[2][mt][nt][f],          p31 = acc[2][mt][nt][f+1];
                float2 v;
                v.x = p10 - p20 + br0;
                v.y = p11 - p21 + br1;
                *(float2*)&Yr[(size_t)row * Esz + col] = v;
                v.x = p30 - p10 - p20 + bi0;
                v.y = p31 - p11 - p21 + bi1;
                *(float2*)&Yi[(size_t)row * Esz + col] = v;
            }
        }
    }
}

// ---------------------------------------------------------------------------
// Tensor-core flash attention (round-11 design, at its mma floor). Epilogue
// writes the o-layer dedup A_cat (4 blocks, width KA3).
// ---------------------------------------------------------------------------
#define AT_STR 144
#define AT_MAT (64 * AT_STR)
#define AT_QMAT (128 * AT_STR)
#define AT_QBYTES (4 * AT_QMAT)              // 73728
#define AT_STAGE (6 * AT_MAT)                // 55296
#define AT_SMEM (AT_QBYTES + 2 * AT_STAGE)   // 184320
#define NKT (Lsz / 64)

__global__ __launch_bounds__(256, 1) void attn_tc_kernel(
    const __nv_bfloat16* __restrict__ QRH, const __nv_bfloat16* __restrict__ QRL,
    const __nv_bfloat16* __restrict__ QIH, const __nv_bfloat16* __restrict__ QIL,
    const __nv_bfloat16* __restrict__ KRH, const __nv_bfloat16* __restrict__ KRL,
    const __nv_bfloat16* __restrict__ KIH, const __nv_bfloat16* __restrict__ KIL,
    const __half* __restrict__ VRH, const __half* __restrict__ VIH,
    __nv_bfloat16* __restrict__ Ao)
{
    extern __shared__ char smem[];
    const uint32_t sb = smem_u32(smem);
    const int tid = threadIdx.x;
    const int lane = tid & 31;
    const int wid = tid >> 5;
    const int q0 = blockIdx.x * 128;
    const int bh = blockIdx.y;
    const size_t pb = (size_t)bh * Lsz * Dsz;

    const __nv_bfloat16* Qm[4] = {QRH + pb, QRL + pb, QIH + pb, QIL + pb};
    const void* Km[6] = {KRH + pb, KRL + pb, KIH + pb, KIL + pb,
                         VRH + pb, VIH + pb};

    #pragma unroll
    for (int mat = 0; mat < 4; ++mat) {
        #pragma unroll
        for (int i = 0; i < 4; ++i) {
            const int op = tid + i * 256;
            const int r = op >> 3, q = op & 7;
            cpa16(sb + mat * AT_QMAT + r * AT_STR + q * 16,
                  Qm[mat] + (size_t)(q0 + r) * Dsz + q * 8);
        }
    }
    CPA_COMMIT();

    auto issue_kv = [&](int kt, int buf) {
        const uint32_t base = sb + AT_QBYTES + buf * AT_STAGE;
        #pragma unroll
        for (int mat = 0; mat < 6; ++mat) {
            #pragma unroll
            for (int i = 0; i < 2; ++i) {
                const int op = tid + i * 256;
                const int r = op >> 3, q = op & 7;
                cpa16(base + mat * AT_MAT + r * AT_STR + q * 16,
                      (const char*)Km[mat] + ((size_t)(kt * 64 + r) * Dsz + q * 8) * 2);
            }
        }
        CPA_COMMIT();
    };

    issue_kv(0, 0);
    CPA_WAIT(0);
    __syncthreads();

    float oR[8][4] = {};
    float oI[8][4] = {};
    float mrun0 = -INFINITY, mrun1 = -INFINITY;
    float lrun0 = 0.f, lrun1 = 0.f;
    const float sc = 0.125f * 1.4426950408889634f;

    const uint32_t aoff = (uint32_t)((wid * 16 + (lane & 15)) * AT_STR + (lane >> 4) * 16);
    const uint32_t boff = (uint32_t)(((lane & 7) + ((lane >> 4) << 3)) * AT_STR
                                     + ((lane >> 3) & 1) * 16);
    const uint32_t voff = (uint32_t)((lane & 15) * AT_STR + (lane >> 4) * 16);

    for (int kt = 0; kt < NKT; ++kt) {
        if (kt + 1 < NKT) { issue_kv(kt + 1, (kt + 1) & 1); CPA_WAIT(1); }
        else CPA_WAIT(0);
        __syncthreads();
        const uint32_t kb = sb + AT_QBYTES + (kt & 1) * AT_STAGE;

        // ---- scores: 6 bf16 hi/lo chains ----
        float sacc[8][4] = {};
        #pragma unroll
        for (int ks = 0; ks < 4; ++ks) {
            uint32_t aq[4][4];
            #pragma unroll
            for (int m = 0; m < 4; ++m)
                ldsm_x4(aq[m], sb + m * AT_QMAT + aoff + ks * 32);
            #pragma unroll
            for (int np = 0; np < 4; ++np) {
                uint32_t kf[4][4];
                #pragma unroll
                for (int m = 0; m < 4; ++m)
                    ldsm_x4(kf[m], kb + m * AT_MAT + boff + np * 16 * AT_STR + ks * 32);
                mma16816(sacc[2*np],   aq[0], &kf[0][0]);
                mma16816(sacc[2*np+1], aq[0], &kf[0][2]);
                mma16816(sacc[2*np],   aq[0], &kf[1][0]);
                mma16816(sacc[2*np+1], aq[0], &kf[1][2]);
                mma16816(sacc[2*np],   aq[1], &kf[0][0]);
                mma16816(sacc[2*np+1], aq[1], &kf[0][2]);
                mma16816(sacc[2*np],   aq[2], &kf[2][0]);
                mma16816(sacc[2*np+1], aq[2], &kf[2][2]);
                mma16816(sacc[2*np],   aq[2], &kf[3][0]);
                mma16816(sacc[2*np+1], aq[2], &kf[3][2]);
                mma16816(sacc[2*np],   aq[3], &kf[2][0]);
                mma16816(sacc[2*np+1], aq[3], &kf[2][2]);
            }
        }

        // ---- online softmax, P -> fp16 ----
        float mt0 = -INFINITY, mt1 = -INFINITY;
        #pragma unroll
        for (int j = 0; j < 8; ++j) {
            mt0 = fmaxf(mt0, fmaxf(sacc[j][0], sacc[j][1]));
            mt1 = fmaxf(mt1, fmaxf(sacc[j][2], sacc[j][3]));
        }
        mt0 = fmaxf(mt0, __shfl_xor_sync(0xffffffffu, mt0, 1));
        mt0 = fmaxf(mt0, __shfl_xor_sync(0xffffffffu, mt0, 2));
        mt1 = fmaxf(mt1, __shfl_xor_sync(0xffffffffu, mt1, 1));
        mt1 = fmaxf(mt1, __shfl_xor_sync(0xffffffffu, mt1, 2));
        const float mn0 = fmaxf(mrun0, mt0 * sc);
        const float mn1 = fmaxf(mrun1, mt1 * sc);

        float rs0 = 0.f, rs1 = 0.f;
        uint32_t ph[4][4];
        #pragma unroll
        for (int j = 0; j < 8; ++j) {
            float p0 = fexp2(fmaf(sacc[j][0], sc, -mn0));
            float p1 = fexp2(fmaf(sacc[j][1], sc, -mn0));
            float p2 = fexp2(fmaf(sacc[j][2], sc, -mn1));
            float p3 = fexp2(fmaf(sacc[j][3], sc, -mn1));
            rs0 += p0 + p1;
            rs1 += p2 + p3;
            const int ks = j >> 1;
            const int hx = (j & 1) * 2;
            ph[ks][hx + 0] = packh2(p0, p1);
            ph[ks][hx + 1] = packh2(p2, p3);
        }

        rs0 += __shfl_xor_sync(0xffffffffu, rs0, 1);
        rs0 += __shfl_xor_sync(0xffffffffu, rs0, 2);
        rs1 += __shfl_xor_sync(0xffffffffu, rs1, 1);
        rs1 += __shfl_xor_sync(0xffffffffu, rs1, 2);
        const float c0 = fexp2(mrun0 - mn0);
        const float c1 = fexp2(mrun1 - mn1);
        lrun0 = lrun0 * c0 + rs0;
        lrun1 = lrun1 * c1 + rs1;
        mrun0 = mn0; mrun1 = mn1;
        #pragma unroll
        for (int j = 0; j < 8; ++j) {
            oR[j][0] *= c0; oR[j][1] *= c0; oR[j][2] *= c1; oR[j][3] *= c1;
            oI[j][0] *= c0; oI[j][1] *= c0; oI[j][2] *= c1; oI[j][3] *= c1;
        }

        // ---- O += P @ V : 2 fp16 chains ----
        #pragma unroll
        for (int ks = 0; ks < 4; ++ks) {
            #pragma unroll
            for (int np = 0; np < 4; ++np) {
                uint32_t vr[4], vi[4];
                ldsm_x4_t(vr, kb + 4 * AT_MAT + voff + ks * 16 * AT_STR + np * 32);
                ldsm_x4_t(vi, kb + 5 * AT_MAT + voff + ks * 16 * AT_STR + np * 32);
                mma16816h(oR[2*np],   ph[ks], &vr[0]);
                mma16816h(oR[2*np+1], ph[ks], &vr[2]);
                mma16816h(oI[2*np],   ph[ks], &vi[0]);
                mma16816h(oI[2*np+1], ph[ks], &vi[2]);
            }
        }
        __syncthreads();
    }

    // finalize: write o-layer dedup A_cat (4 blocks, width KA3)
    const float inv0 = 1.0f / lrun0;
    const float inv1 = 1.0f / lrun1;
    const int b = bh >> 4, h = bh & 15;
    const int row0 = q0 + wid * 16 + (lane >> 2);
    #pragma unroll
    for (int j = 0; j < 8; ++j) {
        const int e = h * 64 + j * 8 + (lane & 3) * 2;
        #pragma unroll
        for (int hf = 0; hf < 2; ++hf) {
            const int l = row0 + hf * 8;
            const float inv = (hf == 0) ? inv0 : inv1;
            const int f = hf * 2;
            const float yr0 = oR[j][f] * inv,  yr1 = oR[j][f+1] * inv;
            const float yi0 = oI[j][f] * inv,  yi1 = oI[j][f+1] * inv;
            const float ys0 = yr0 + yi0, ys1 = yr1 + yi1;
            __nv_bfloat16* base = Ao + (size_t)(b * Lsz + l) * KA3 + e;
            __nv_bfloat16 h0, l0, h1, l1;
            split1(ys0, h0, l0); split1(ys1, h1, l1);
            *(uint32_t*)(base + 0)    = packh2(yr0, yr1);
            *(uint32_t*)(base + 1024) = packh2(yi0, yi1);
            *(uint32_t*)(base + 2048) = packbf2(h0, h1);
            *(uint32_t*)(base + 3072) = packbf2(l0, l1);
        }
    }
}

// ---------------------------------------------------------------------------
extern "C" void kernel_launch(void* const* d_in, const int* in_sizes, int n_in,
                              void* d_out, int out_size)
{
    (void)in_sizes; (void)n_in; (void)out_size;
    const float* query_r = (const float*)d_in[0];
    const float* query_i = (const float*)d_in[1];
    const float* key_r   = (const float*)d_in[2];
    const float* key_i   = (const float*)d_in[3];
    const float* value_r = (const float*)d_in[4];
    const float* value_i = (const float*)d_in[5];
    const float* Wq_r = (const float*)d_in[6];
    const float* Wq_i = (const float*)d_in[7];
    const float* bq_r = (const float*)d_in[8];
    const float* bq_i = (const float*)d_in[9];
    const float* Wk_r = (const float*)d_in[10];
    const float* Wk_i = (const float*)d_in[11];
    const float* bk_r = (const float*)d_in[12];
    const float* bk_i = (const float*)d_in[13];
    const float* Wv_r = (const float*)d_in[14];
    const float* Wv_i = (const float*)d_in[15];
    const float* bv_r = (const float*)d_in[16];
    const float* bv_i = (const float*)d_in[17];
    const float* Wo_r = (const float*)d_in[18];
    const float* Wo_i = (const float*)d_in[19];
    const float* bo_r = (const float*)d_in[20];
    const float* bo_i = (const float*)d_in[21];

    __nv_bfloat16* acat = nullptr;
    cudaGetSymbolAddress((void**)&acat, g_acat);
    __nv_bfloat16* bcat = nullptr;
    cudaGetSymbolAddress((void**)&bcat, g_bcat);
    __nv_bfloat16* attn = nullptr;
    cudaGetSymbolAddress((void**)&attn, g_attn);

    auto Wc = [&](int s) { return bcat + (size_t)s * Esz * KE3; };
    auto Ac = [&](int s) { return acat + (size_t)s * NROW * KA3; };
    auto At = [&](int s) { return attn + (size_t)s * BHD; };

    SplitWBatch wb;
    wb.Wr[0] = Wq_r; wb.Wi[0] = Wq_i; wb.B[0] = Wc(0);
    wb.Wr[1] = Wk_r; wb.Wi[1] = Wk_i; wb.B[1] = Wc(1);
    wb.Wr[2] = Wv_r; wb.Wi[2] = Wv_i; wb.B[2] = Wc(2);
    wb.Wr[3] = Wo_r; wb.Wi[3] = Wo_i; wb.B[3] = Wc(3);
    splitW_kernel<<<dim3(256, 1, 4), 256>>>(wb);

    SplitABatch ab;
    ab.Xr[0] = query_r; ab.Xi[0] = query_i; ab.A[0] = Ac(0);
    ab.Xr[1] = key_r;   ab.Xi[1] = key_i;   ab.A[1] = Ac(1);
    ab.Xr[2] = value_r; ab.Xi[2] = value_i; ab.A[2] = Ac(2);
    splitA_kernel<<<dim3(384, 1, 3), 256>>>(ab);

    QKVBatch batch;
    batch.A[0] = Ac(0); batch.A[1] = Ac(1); batch.A[2] = Ac(2);
    batch.B[0] = Wc(0); batch.B[1] = Wc(1); batch.B[2] = Wc(2);
    batch.br[0] = bq_r; batch.bi[0] = bq_i;
    batch.br[1] = bk_r; batch.bi[1] = bk_i;
    batch.br[2] = bv_r; batch.bi[2] = bv_i;
    batch.RH[0] = At(0); batch.RL[0] = At(1); batch.IH[0] = At(2); batch.IL[0] = At(3);
    batch.RH[1] = At(4); batch.RL[1] = At(5); batch.IH[1] = At(6); batch.IL[1] = At(7);
    batch.RH[2] = At(8); batch.IH[2] = At(9); batch.RL[2] = At(8); batch.IL[2] = At(9);

    cudaFuncSetAttribute((const void*)gemm_qkv_kernel,
                         cudaFuncAttributeMaxDynamicSharedMemorySize, GEMM_SMEM);
    cudaFuncSetAttribute((const void*)gemm_kernel,
                         cudaFuncAttributeMaxDynamicSharedMemorySize, GEMM_SMEM);

    gemm_qkv_kernel<<<dim3(Esz / GN, NROW / GM, 3), GTHR, GEMM_SMEM>>>(batch);

    cudaFuncSetAttribute((const void*)attn_tc_kernel,
                         cudaFuncAttributeMaxDynamicSharedMemorySize, AT_SMEM);
    attn_tc_kernel<<<dim3(Lsz / 128, Bsz * Hsz), 256, AT_SMEM>>>(
        At(0), At(1), At(2), At(3), At(4), At(5), At(6), At(7),
        (const __half*)At(8), (const __half*)At(9), Ac(0));

    float* yr = (float*)d_out;
    float* yi = yr + BLE;
    gemm_kernel<<<dim3(Esz / GN, NROW / GM), GTHR, GEMM_SMEM>>>(
        Ac(0), Wc(3), bo_r, bo_i, yr, yi);
}